// round 13
// baseline (speedup 1.0000x reference)
#include <cuda_runtime.h>
#include <math.h>

#define BATCH 16
#define HW 65536

// ---- scratch (device globals) ----
__device__ float dS[BATCH*HW];
__device__ float dPmn[BATCH*8*64];   // per-block min partials [b][o][blk64]
__device__ float dPmx[BATCH*8*64];
__device__ float dHist[4096];
__device__ float dTotal;
__device__ float dR0[BATCH*64*168];
__device__ float dR1[BATCH*64*168];
__device__ float dR2[BATCH*64*168];

__device__ __forceinline__ float lrelu(float v){ return v >= 0.f ? v : 0.01f*v; }

// ---- K1: fused box-pool (separable) + LBP min/max; 32x32 tile; 4-px register strips ----
__global__ void __launch_bounds__(256) k_pool_minmax(const float* __restrict__ x,
                                                     const float* __restrict__ clo,
                                                     const float* __restrict__ chi){
    __shared__ float xs[36][40];   // rows h0-2..h0+33, cols w0-4..w0+35
    __shared__ float hs[36][34];   // horizontal 3-sums, cols w0-1..w0+32
    __shared__ float St[34][40];   // pooled S, rows h0-1..h0+32; valid cols 3..36 (w0-1..w0+32)
    __shared__ float red[8][16];
    int b  = blockIdx.z;
    int h0 = blockIdx.y*32, w0 = blockIdx.x*32;
    int tid = threadIdx.x;
    const float* xb = x + (size_t)b*3*HW;

    if (blockIdx.x == 0 && blockIdx.y == 0){
        dHist[b*256 + tid] = 0.f;
        if (b == 0 && tid == 0) dTotal = 0.f;
    }

    for (int i = tid; i < 360; i += 256){
        int r = i/10, c4 = i - r*10;
        int gh = h0-2+r, gw = w0-4+c4*4;
        float4 v = make_float4(0.f,0.f,0.f,0.f);
        if ((unsigned)gh < 256u && gw >= 0 && gw <= 252){
            const float* p0 = xb + (gh<<8) + gw;
            float4 a = *(const float4*)p0;
            float4 bb = *(const float4*)(p0 + HW);
            float4 cc = *(const float4*)(p0 + 2*HW);
            v.x = a.x+bb.x+cc.x; v.y = a.y+bb.y+cc.y;
            v.z = a.z+bb.z+cc.z; v.w = a.w+bb.w+cc.w;
        }
        xs[r][c4*4+0] = v.x; xs[r][c4*4+1] = v.y;
        xs[r][c4*4+2] = v.z; xs[r][c4*4+3] = v.w;
    }
    __syncthreads();

    for (int i = tid; i < 1224; i += 256){
        int r = i/34, c = i - r*34;
        hs[r][c] = xs[r][c+2] + xs[r][c+3] + xs[r][c+4];
    }
    __syncthreads();

    for (int i = tid; i < 1156; i += 256){
        int r = i/34, c = i - r*34;
        int h = h0-1+r, w = w0-1+c;
        float s = 0.f;
        if ((unsigned)h < 256u && (unsigned)w < 256u)
            s = (hs[r][c] + hs[r+1][c] + hs[r+2][c]) / 9.0f;
        St[r][c+3] = s;
    }
    __syncthreads();

    // write dS interior with aligned smem float4 reads
    {
        int r = tid >> 3, c4 = tid & 7;
        float4 v = *(float4*)&St[r+1][4 + c4*4];
        *(float4*)&dS[b*HW + ((h0+r)<<8) + w0 + c4*4] = v;
    }

    // 4-pixel strip min/max: thread row r=(tid>>3)+1, cols c0..c0+3 with c0=(tid&7)*4+4
    const int DY[8] = {-1,1,-1,1,-1,1,0,0};
    const int DX[8] = {-1,1,0,0,1,-1,1,-1};
    float lo = clo[0], hi = chi[0];
    float mn[8], mx[8];
    #pragma unroll
    for (int o = 0; o < 8; o++){ mn[o] = 3.4e38f; mx[o] = -3.4e38f; }
    {
        int r  = (tid >> 3) + 1;
        int c0 = (tid & 7)*4 + 4;
        float a[3][6];
        #pragma unroll
        for (int dr = 0; dr < 3; dr++){
            const float* row = &St[r-1+dr][0];
            float4 m = *(const float4*)&row[c0];
            a[dr][0] = row[c0-1];
            a[dr][1] = m.x; a[dr][2] = m.y; a[dr][3] = m.z; a[dr][4] = m.w;
            a[dr][5] = row[c0+4];
        }
        #pragma unroll
        for (int j = 0; j < 4; j++){
            float ctr = a[1][j+1];
            #pragma unroll
            for (int o = 0; o < 8; o++){
                float v = fminf(fmaxf(ctr - a[1+DY[o]][j+1+DX[o]], lo), hi);
                mn[o] = fminf(mn[o], v);
                mx[o] = fmaxf(mx[o], v);
            }
        }
    }
    #pragma unroll
    for (int o = 0; o < 8; o++){
        #pragma unroll
        for (int off = 16; off; off >>= 1){
            mn[o] = fminf(mn[o], __shfl_xor_sync(0xffffffffu, mn[o], off));
            mx[o] = fmaxf(mx[o], __shfl_xor_sync(0xffffffffu, mx[o], off));
        }
    }
    int warp = tid >> 5, lane = tid & 31;
    if (lane == 0){
        #pragma unroll
        for (int o = 0; o < 8; o++){ red[warp][o] = mn[o]; red[warp][8+o] = mx[o]; }
    }
    __syncthreads();
    int blk = blockIdx.y*8 + blockIdx.x;   // 0..63 within batch
    if (tid < 16){
        if (tid < 8){
            float v = red[0][tid];
            #pragma unroll
            for (int w2 = 1; w2 < 8; w2++) v = fminf(v, red[w2][tid]);
            dPmn[(b*8 + tid)*64 + blk] = v;
        } else {
            float v = red[0][tid];
            #pragma unroll
            for (int w2 = 1; w2 < 8; w2++) v = fmaxf(v, red[w2][tid]);
            dPmx[(b*8 + tid - 8)*64 + blk] = v;
        }
    }
}

// ---- K2: product histogram + global total; 32x32 tile; 4-px register strips ----
__global__ void __launch_bounds__(256) k_hist(const float* __restrict__ clo,
                                              const float* __restrict__ chi){
    __shared__ float Sh[34][40];     // rows h0-1..h0+32, cols w0-4..w0+35
    __shared__ float sh[8][256];
    __shared__ float lv[8][8];
    __shared__ float smn[8], sscale[8];
    __shared__ float rawmn[8], rawmx[8];
    __shared__ float redt[8];
    int b  = blockIdx.z;
    int h0 = blockIdx.y*32, w0 = blockIdx.x*32;
    int tid = threadIdx.x;
    int warp = tid >> 5, lane = tid & 31;
    const float* Sb = dS + b*HW;

    {
        const float* pmn = &dPmn[(b*8 + warp)*64];
        const float* pmx = &dPmx[(b*8 + warp)*64];
        float mn = fminf(pmn[lane], pmn[lane+32]);
        float mx = fmaxf(pmx[lane], pmx[lane+32]);
        #pragma unroll
        for (int off = 16; off; off >>= 1){
            mn = fminf(mn, __shfl_xor_sync(0xffffffffu, mn, off));
            mx = fmaxf(mx, __shfl_xor_sync(0xffffffffu, mx, off));
        }
        if (lane == 0){ rawmn[warp] = mn; rawmx[warp] = mx; }
    }

    for (int i = tid; i < 340; i += 256){
        int r = i/10, c4 = i - r*10;
        int gh = h0-1+r, gw = w0-4+c4*4;
        float4 v = make_float4(0.f,0.f,0.f,0.f);
        if ((unsigned)gh < 256u && gw >= 0 && gw <= 252)
            v = *(const float4*)(Sb + (gh<<8) + gw);
        Sh[r][c4*4+0] = v.x; Sh[r][c4*4+1] = v.y;
        Sh[r][c4*4+2] = v.z; Sh[r][c4*4+3] = v.w;
    }
    for (int i = tid; i < 2048; i += 256) ((float*)sh)[i] = 0.f;
    __syncthreads();

    if (tid < 64){
        int o = tid >> 3, q = tid & 7;
        float mnv = rawmn[o], mxv = rawmx[o];
        float r = mxv - mnv;
        lv[o][q] = __fadd_rn(mnv, __fmul_rn(r, q*0.125f));
        if (q == 0){ smn[o] = mnv; sscale[o] = (r > 0.f) ? 8.0f/r : 0.f; }
    }
    __syncthreads();

    const int DY[8] = {-1,1,-1,1,-1,1,0,0};
    const int DX[8] = {-1,1,0,0,1,-1,1,-1};
    float lo = clo[0], hic = chi[0];

    // 4-pixel strip: thread row r=(tid>>3)+1, center cols c0..c0+3 with c0=(tid&7)*4+4
    {
        int r  = (tid >> 3) + 1;
        int c0 = (tid & 7)*4 + 4;
        float a[3][6];
        #pragma unroll
        for (int dr = 0; dr < 3; dr++){
            const float* row = &Sh[r-1+dr][0];
            float4 m = *(const float4*)&row[c0];
            a[dr][0] = row[c0-1];
            a[dr][1] = m.x; a[dr][2] = m.y; a[dr][3] = m.z; a[dr][4] = m.w;
            a[dr][5] = row[c0+4];
        }
        #pragma unroll
        for (int j = 0; j < 4; j++){
            float ctr = a[1][j+1];
            float vv[8]; int qq[8]; unsigned tie = 0;
            #pragma unroll
            for (int o = 0; o < 8; o++){
                float v = fminf(fmaxf(ctr - a[1+DY[o]][j+1+DX[o]], lo), hic);
                float f = (v - smn[o]) * sscale[o];
                int q = (int)f; q = q < 0 ? 0 : (q > 7 ? 7 : q);
                if (q < 7 && v >= lv[o][q+1]) q++;
                if (q > 0 && v <  lv[o][q])   q--;
                vv[o] = v; qq[o] = q;
                if (q > 0 && v == lv[o][q]) tie |= 1u << o;
            }
            #pragma unroll
            for (int g = 0; g < 4; g++){
                float prod = vv[2*g] * vv[2*g+1];
                int qi = qq[2*g], qj = qq[2*g+1];
                atomicAdd(&sh[warp][g*64 + qi*8 + qj], prod);
                if (tie & (3u << (2*g))){
                    if (tie & (1u << (2*g)))   atomicAdd(&sh[warp][g*64 + (qi-1)*8 + qj], prod);
                    if (tie & (1u << (2*g+1))) atomicAdd(&sh[warp][g*64 + qi*8 + (qj-1)], prod);
                    if (((tie >> (2*g)) & 3u) == 3u)
                                               atomicAdd(&sh[warp][g*64 + (qi-1)*8 + (qj-1)], prod);
                }
            }
        }
    }
    __syncthreads();

    float s;
    {
        int g = tid >> 6, bin = tid & 63;
        s = sh[0][g*64+bin] + sh[1][g*64+bin] + sh[2][g*64+bin] + sh[3][g*64+bin]
          + sh[4][g*64+bin] + sh[5][g*64+bin] + sh[6][g*64+bin] + sh[7][g*64+bin];
        atomicAdd(&dHist[(b*4+g)*64 + bin], s);
    }
    #pragma unroll
    for (int off = 16; off; off >>= 1) s += __shfl_xor_sync(0xffffffffu, s, off);
    if (lane == 0) redt[warp] = s;
    __syncthreads();
    if (tid == 0){
        float t = 0.f;
        #pragma unroll
        for (int w2 = 0; w2 < 8; w2++) t += redt[w2];
        atomicAdd(&dTotal, t);
    }
}

// ---- K3: expand-conv + instance-norm + 4->16 conv + wf row-contraction ----
__global__ void __launch_bounds__(256) k_grid(const float* __restrict__ we,
                                              const float* __restrict__ be,
                                              const float* __restrict__ wc,
                                              const float* __restrict__ bc,
                                              const float* __restrict__ wf){
    __shared__ float hist_s[256];
    __shared__ float we_s[168], be_s[56], wc_s[64], bc_s[16], wf_s[144];
    __shared__ float sred[8][8];
    __shared__ float mean_s[4], inv_s[4];
    int b = blockIdx.x >> 3, q = blockIdx.x & 7;
    int tid = threadIdx.x;
    int warp = tid >> 5, lane = tid & 31;

    hist_s[tid] = dHist[b*256 + tid];
    if (tid < 168) we_s[tid] = we[tid];
    if (tid < 56)  be_s[tid] = be[tid];
    if (tid < 64)  wc_s[tid] = wc[tid];
    if (tid < 16)  bc_s[tid] = bc[tid];
    if (tid < 144) wf_s[tid] = wf[tid];
    __syncthreads();
    float total = dTotal;

    float s[4] = {0,0,0,0}, sq[4] = {0,0,0,0};
    for (int e = tid; e < 3584; e += 256){
        int p = e / 56, oc = e - p*56;
        int cnt = (((oc+1)*256 + 55)/56) - ((oc*256 + 55)/56);
        float wgt = (float)(cnt*4);
        float base = we_s[oc*3+0]*(float)(p>>3) + we_s[oc*3+1]*(float)(p&7) + be_s[oc];
        float w2 = we_s[oc*3+2];
        #pragma unroll
        for (int g = 0; g < 4; g++){
            float hn = hist_s[g*64+p] / total;
            float y = lrelu(base + w2*hn);
            s[g]  += y*wgt;
            sq[g] += y*y*wgt;
        }
    }
    #pragma unroll
    for (int g = 0; g < 4; g++){
        #pragma unroll
        for (int off = 16; off; off >>= 1){
            s[g]  += __shfl_xor_sync(0xffffffffu, s[g],  off);
            sq[g] += __shfl_xor_sync(0xffffffffu, sq[g], off);
        }
    }
    if (lane == 0){
        #pragma unroll
        for (int g = 0; g < 4; g++){ sred[warp][g] = s[g]; sred[warp][4+g] = sq[g]; }
    }
    __syncthreads();
    if (tid < 4){
        float ts = 0.f, tq = 0.f;
        #pragma unroll
        for (int w2 = 0; w2 < 8; w2++){ ts += sred[w2][tid]; tq += sred[w2][4+tid]; }
        float mean = ts / 65536.f;
        float var  = tq / 65536.f - mean*mean;
        mean_s[tid] = mean;
        inv_s[tid]  = 1.f / sqrtf(fmaxf(var, 0.f) + 1e-5f);
    }
    __syncthreads();

    float m0 = mean_s[0], m1 = mean_s[1], m2 = mean_s[2], m3 = mean_s[3];
    float i0 = inv_s[0],  i1 = inv_s[1],  i2 = inv_s[2],  i3 = inv_s[3];
    for (int e = q*448 + tid; e < (q+1)*448; e += 256){
        int p = e / 56, oc = e - p*56;
        float base = we_s[oc*3+0]*(float)(p>>3) + we_s[oc*3+1]*(float)(p&7) + be_s[oc];
        float w2 = we_s[oc*3+2];
        float t[4];
        t[0] = (lrelu(base + w2*(hist_s[0*64+p]/total)) - m0) * i0;
        t[1] = (lrelu(base + w2*(hist_s[1*64+p]/total)) - m1) * i1;
        t[2] = (lrelu(base + w2*(hist_s[2*64+p]/total)) - m2) * i2;
        t[3] = (lrelu(base + w2*(hist_s[3*64+p]/total)) - m3) * i3;
        float r[3][3] = {{0,0,0},{0,0,0},{0,0,0}};
        #pragma unroll
        for (int m = 0; m < 16; m++){
            float zm = lrelu(bc_s[m] + wc_s[m*4]*t[0] + wc_s[m*4+1]*t[1]
                                     + wc_s[m*4+2]*t[2] + wc_s[m*4+3]*t[3]);
            #pragma unroll
            for (int i = 0; i < 3; i++){
                r[i][0] += zm * wf_s[m*9 + i*3 + 0];
                r[i][1] += zm * wf_s[m*9 + i*3 + 1];
                r[i][2] += zm * wf_s[m*9 + i*3 + 2];
            }
        }
        int idx = b*64*168 + p*168 + oc*3;
        dR0[idx] = r[0][0]; dR0[idx+1] = r[0][1]; dR0[idx+2] = r[0][2];
        dR1[idx] = r[1][0]; dR1[idx+1] = r[1][1]; dR1[idx+2] = r[1][2];
        dR2[idx] = r[2][0]; dR2[idx+1] = r[2][1]; dR2[idx+2] = r[2][2];
    }
}

// ---- K4: final conv — tap tables from row-sums; vectorized output stores ----
__global__ void __launch_bounds__(256) k_final(const float* __restrict__ bf,
                                               float* __restrict__ out){
    __shared__ float u[3][168];
    __shared__ float obuf[3][256];
    int t = blockIdx.x, b = blockIdx.y;
    int tid = threadIdx.x;
    int rowbase = b*64*168 + t*168;

    for (int e = tid; e < 504; e += 256){
        int tbl = e / 168, k = e - tbl*168;
        float acc;
        if (tbl == 0){
            acc = dR1[rowbase + k] + dR2[rowbase + k];
            if (t > 0) acc += dR0[rowbase - 168 + k];
        } else if (tbl == 1){
            acc = dR0[rowbase + k] + dR1[rowbase + k] + dR2[rowbase + k];
        } else {
            acc = dR0[rowbase + k] + dR1[rowbase + k];
            if (t < 63) acc += dR2[rowbase + 168 + k];
        }
        u[tbl][k] = acc;
    }
    __syncthreads();

    {
        int w = tid;
        int gwC = (w*56) >> 8;
        int gwL = ((w-1)*56) >> 8;
        int gwR = ((w+1)*56) >> 8;
        float base = bf[0];
        #pragma unroll
        for (int tbl = 0; tbl < 3; tbl++){
            float acc = base + u[tbl][gwC*3 + 1];
            if (w > 0)   acc += u[tbl][gwL*3 + 0];
            if (w < 255) acc += u[tbl][gwR*3 + 2];
            obuf[tbl][w] = lrelu(acc);
        }
    }
    __syncthreads();

    {
        int r = tid >> 6, c4 = tid & 63;
        int src = (r == 0) ? 0 : (r == 3 ? 2 : 1);
        float4 v = ((float4*)obuf[src])[c4];
        *(float4*)&out[((size_t)b << 16) | ((size_t)(t*4+r) << 8) | (size_t)(c4*4)] = v;
    }
}

extern "C" void kernel_launch(void* const* d_in, const int* in_sizes, int n_in,
                              void* d_out, int out_size){
    const float* x    = (const float*)d_in[0];
    const float* we   = (const float*)d_in[1];
    const float* be   = (const float*)d_in[2];
    const float* wc   = (const float*)d_in[3];
    const float* bc   = (const float*)d_in[4];
    const float* wfin = (const float*)d_in[5];
    const float* bfin = (const float*)d_in[6];
    const float* clo  = (const float*)d_in[7];
    const float* chi  = (const float*)d_in[8];
    float* out = (float*)d_out;

    k_pool_minmax<<<dim3(8,8,16), 256>>>(x, clo, chi);
    k_hist       <<<dim3(8,8,16), 256>>>(clo, chi);
    k_grid       <<<128, 256>>>(we, be, wc, bc, wfin);
    k_final      <<<dim3(64,16), 256>>>(bfin, out);
}

// round 14
// speedup vs baseline: 1.1158x; 1.1158x over previous
#include <cuda_runtime.h>
#include <math.h>

#define BATCH 16
#define HW 65536

// ---- scratch (device globals) ----
__device__ float dS[BATCH*HW];
__device__ float dPmn[BATCH*8*64];   // per-block min partials [b][o][blk64]
__device__ float dPmx[BATCH*8*64];
__device__ float dHist[4096];
__device__ float dTotal;
__device__ float dMean[64];
__device__ float dInv[64];

__device__ __forceinline__ float lrelu(float v){ return v >= 0.f ? v : 0.01f*v; }

// ---- K1: fused box-pool (channel sum, separable) + per-orientation LBP block min/max ----
__global__ void __launch_bounds__(256) k_pool_minmax(const float* __restrict__ x,
                                                     const float* __restrict__ clo,
                                                     const float* __restrict__ chi){
    __shared__ float xs[36][40];
    __shared__ float hs[36][34];
    __shared__ float St[34][34];
    __shared__ float red[8][16];
    int b  = blockIdx.z;
    int h0 = blockIdx.y*32, w0 = blockIdx.x*32;
    int tid = threadIdx.x;
    int tx = tid & 31, ty = tid >> 5;
    const float* xb = x + (size_t)b*3*HW;

    if (blockIdx.x == 0 && blockIdx.y == 0){
        dHist[b*256 + tid] = 0.f;
        if (b == 0 && tid == 0) dTotal = 0.f;
    }

    for (int i = tid; i < 360; i += 256){
        int r = i/10, c4 = i - r*10;
        int gh = h0-2+r, gw = w0-4+c4*4;
        float4 v = make_float4(0.f,0.f,0.f,0.f);
        if ((unsigned)gh < 256u && gw >= 0 && gw <= 252){
            const float* p0 = xb + (gh<<8) + gw;
            float4 a = *(const float4*)p0;
            float4 bb = *(const float4*)(p0 + HW);
            float4 cc = *(const float4*)(p0 + 2*HW);
            v.x = a.x+bb.x+cc.x; v.y = a.y+bb.y+cc.y;
            v.z = a.z+bb.z+cc.z; v.w = a.w+bb.w+cc.w;
        }
        xs[r][c4*4+0] = v.x; xs[r][c4*4+1] = v.y;
        xs[r][c4*4+2] = v.z; xs[r][c4*4+3] = v.w;
    }
    __syncthreads();

    for (int i = tid; i < 1224; i += 256){
        int r = i/34, c = i - r*34;
        hs[r][c] = xs[r][c+2] + xs[r][c+3] + xs[r][c+4];
    }
    __syncthreads();

    for (int i = tid; i < 1156; i += 256){
        int r = i/34, c = i - r*34;
        int h = h0-1+r, w = w0-1+c;
        float s = 0.f;
        if ((unsigned)h < 256u && (unsigned)w < 256u)
            s = (hs[r][c] + hs[r+1][c] + hs[r+2][c]) / 9.0f;
        St[r][c] = s;
    }
    __syncthreads();

    {
        int r = tid >> 3, c4 = tid & 7;
        float4 v;
        v.x = St[r+1][1+c4*4]; v.y = St[r+1][2+c4*4];
        v.z = St[r+1][3+c4*4]; v.w = St[r+1][4+c4*4];
        *(float4*)&dS[b*HW + ((h0+r)<<8) + w0 + c4*4] = v;
    }

    const int DY[8] = {-1,1,-1,1,-1,1,0,0};
    const int DX[8] = {-1,1,0,0,1,-1,1,-1};
    float lo = clo[0], hi = chi[0];
    float mn[8], mx[8];
    #pragma unroll
    for (int o = 0; o < 8; o++){ mn[o] = 3.4e38f; mx[o] = -3.4e38f; }

    #pragma unroll
    for (int ph = 0; ph < 4; ph++){
        int r = ty + ph*8 + 1, c = tx + 1;
        float ctr = St[r][c];
        #pragma unroll
        for (int o = 0; o < 8; o++){
            float v = fminf(fmaxf(ctr - St[r+DY[o]][c+DX[o]], lo), hi);
            mn[o] = fminf(mn[o], v);
            mx[o] = fmaxf(mx[o], v);
        }
    }
    #pragma unroll
    for (int o = 0; o < 8; o++){
        #pragma unroll
        for (int off = 16; off; off >>= 1){
            mn[o] = fminf(mn[o], __shfl_xor_sync(0xffffffffu, mn[o], off));
            mx[o] = fmaxf(mx[o], __shfl_xor_sync(0xffffffffu, mx[o], off));
        }
    }
    int warp = ty, lane = tx;
    if (lane == 0){
        #pragma unroll
        for (int o = 0; o < 8; o++){ red[warp][o] = mn[o]; red[warp][8+o] = mx[o]; }
    }
    __syncthreads();
    int blk = blockIdx.y*8 + blockIdx.x;
    if (tid < 16){
        if (tid < 8){
            float v = red[0][tid];
            #pragma unroll
            for (int w2 = 1; w2 < 8; w2++) v = fminf(v, red[w2][tid]);
            dPmn[(b*8 + tid)*64 + blk] = v;
        } else {
            float v = red[0][tid];
            #pragma unroll
            for (int w2 = 1; w2 < 8; w2++) v = fmaxf(v, red[w2][tid]);
            dPmx[(b*8 + tid - 8)*64 + blk] = v;
        }
    }
}

// ---- K2: product histogram + global total ----
__global__ void __launch_bounds__(256) k_hist(const float* __restrict__ clo,
                                              const float* __restrict__ chi){
    __shared__ float Sh[34][40];
    __shared__ float sh[8][256];
    __shared__ float lv[8][8];
    __shared__ float smn[8], sscale[8];
    __shared__ float rawmn[8], rawmx[8];
    __shared__ float redt[8];
    int b  = blockIdx.z;
    int h0 = blockIdx.y*32, w0 = blockIdx.x*32;
    int tid = threadIdx.x;
    int warp = tid >> 5, lane = tid & 31;
    const float* Sb = dS + b*HW;

    {
        const float* pmn = &dPmn[(b*8 + warp)*64];
        const float* pmx = &dPmx[(b*8 + warp)*64];
        float mn = fminf(pmn[lane], pmn[lane+32]);
        float mx = fmaxf(pmx[lane], pmx[lane+32]);
        #pragma unroll
        for (int off = 16; off; off >>= 1){
            mn = fminf(mn, __shfl_xor_sync(0xffffffffu, mn, off));
            mx = fmaxf(mx, __shfl_xor_sync(0xffffffffu, mx, off));
        }
        if (lane == 0){ rawmn[warp] = mn; rawmx[warp] = mx; }
    }

    for (int i = tid; i < 340; i += 256){
        int r = i/10, c4 = i - r*10;
        int gh = h0-1+r, gw = w0-4+c4*4;
        float4 v = make_float4(0.f,0.f,0.f,0.f);
        if ((unsigned)gh < 256u && gw >= 0 && gw <= 252)
            v = *(const float4*)(Sb + (gh<<8) + gw);
        Sh[r][c4*4+0] = v.x; Sh[r][c4*4+1] = v.y;
        Sh[r][c4*4+2] = v.z; Sh[r][c4*4+3] = v.w;
    }
    for (int i = tid; i < 2048; i += 256) ((float*)sh)[i] = 0.f;
    __syncthreads();

    if (tid < 64){
        int o = tid >> 3, q = tid & 7;
        float mnv = rawmn[o], mxv = rawmx[o];
        float r = mxv - mnv;
        lv[o][q] = __fadd_rn(mnv, __fmul_rn(r, q*0.125f));
        if (q == 0){ smn[o] = mnv; sscale[o] = (r > 0.f) ? 8.0f/r : 0.f; }
    }
    __syncthreads();

    const int DY[8] = {-1,1,-1,1,-1,1,0,0};
    const int DX[8] = {-1,1,0,0,1,-1,1,-1};
    float lo = clo[0], hic = chi[0];
    int tx = tid & 31, ty = tid >> 5;

    #pragma unroll
    for (int ph = 0; ph < 4; ph++){
        int r = ty + ph*8 + 1, cc = tx + 4;
        float ctr = Sh[r][cc];
        float vv[8]; int qq[8]; unsigned tie = 0;
        #pragma unroll
        for (int o = 0; o < 8; o++){
            float v = fminf(fmaxf(ctr - Sh[r+DY[o]][cc+DX[o]], lo), hic);
            float f = (v - smn[o]) * sscale[o];
            int q = (int)f; q = q < 0 ? 0 : (q > 7 ? 7 : q);
            if (q < 7 && v >= lv[o][q+1]) q++;
            if (q > 0 && v <  lv[o][q])   q--;
            vv[o] = v; qq[o] = q;
            if (q > 0 && v == lv[o][q]) tie |= 1u << o;
        }
        #pragma unroll
        for (int g = 0; g < 4; g++){
            float prod = vv[2*g] * vv[2*g+1];
            int qi = qq[2*g], qj = qq[2*g+1];
            atomicAdd(&sh[warp][g*64 + qi*8 + qj], prod);
            if (tie & (3u << (2*g))){
                if (tie & (1u << (2*g)))   atomicAdd(&sh[warp][g*64 + (qi-1)*8 + qj], prod);
                if (tie & (1u << (2*g+1))) atomicAdd(&sh[warp][g*64 + qi*8 + (qj-1)], prod);
                if (((tie >> (2*g)) & 3u) == 3u)
                                           atomicAdd(&sh[warp][g*64 + (qi-1)*8 + (qj-1)], prod);
            }
        }
    }
    __syncthreads();

    float s;
    {
        int g = tid >> 6, bin = tid & 63;
        s = sh[0][g*64+bin] + sh[1][g*64+bin] + sh[2][g*64+bin] + sh[3][g*64+bin]
          + sh[4][g*64+bin] + sh[5][g*64+bin] + sh[6][g*64+bin] + sh[7][g*64+bin];
        atomicAdd(&dHist[(b*4+g)*64 + bin], s);
    }
    #pragma unroll
    for (int off = 16; off; off >>= 1) s += __shfl_xor_sync(0xffffffffu, s, off);
    if (lane == 0) redt[warp] = s;
    __syncthreads();
    if (tid == 0){
        float t = 0.f;
        #pragma unroll
        for (int w2 = 0; w2 < 8; w2++) t += redt[w2];
        atomicAdd(&dTotal, t);
    }
}

// ---- K3: instance-norm stats only. One block per (b,g); same FP order as before ----
__global__ void __launch_bounds__(256) k_stats(const float* __restrict__ we,
                                               const float* __restrict__ be){
    __shared__ float hrow[64];
    __shared__ float we_s[168], be_s[56];
    __shared__ float sred[8][2];
    int b = blockIdx.x >> 2, g = blockIdx.x & 3;
    int tid = threadIdx.x;
    int warp = tid >> 5, lane = tid & 31;

    if (tid < 64)  hrow[tid] = dHist[(b*4+g)*64 + tid];
    if (tid < 168) we_s[tid] = we[tid];
    if (tid < 56)  be_s[tid] = be[tid];
    __syncthreads();
    float total = dTotal;

    float s = 0.f, sq = 0.f;
    for (int e = tid; e < 3584; e += 256){
        int p = e / 56, oc = e - p*56;
        int cnt = (((oc+1)*256 + 55)/56) - ((oc*256 + 55)/56);
        float wgt = (float)(cnt*4);
        float base = we_s[oc*3+0]*(float)(p>>3) + we_s[oc*3+1]*(float)(p&7) + be_s[oc];
        float w2 = we_s[oc*3+2];
        float hn = hrow[p] / total;
        float y = lrelu(base + w2*hn);
        s  += y*wgt;
        sq += y*y*wgt;
    }
    #pragma unroll
    for (int off = 16; off; off >>= 1){
        s  += __shfl_xor_sync(0xffffffffu, s,  off);
        sq += __shfl_xor_sync(0xffffffffu, sq, off);
    }
    if (lane == 0){ sred[warp][0] = s; sred[warp][1] = sq; }
    __syncthreads();
    if (tid == 0){
        float ts = 0.f, tq = 0.f;
        #pragma unroll
        for (int w2 = 0; w2 < 8; w2++){ ts += sred[w2][0]; tq += sred[w2][1]; }
        float mean = ts / 65536.f;
        float var  = tq / 65536.f - mean*mean;
        dMean[b*4+g] = mean;
        dInv[b*4+g]  = 1.f / sqrtf(fmaxf(var, 0.f) + 1e-5f);
    }
}

// ---- K4: final conv — compute row-sums in-block from hist+stats, then tap tables ----
__global__ void __launch_bounds__(256) k_final(const float* __restrict__ we,
                                               const float* __restrict__ be,
                                               const float* __restrict__ wc,
                                               const float* __restrict__ bc,
                                               const float* __restrict__ wf,
                                               const float* __restrict__ bf,
                                               float* __restrict__ out){
    __shared__ float hist_s[256];
    __shared__ float we_s[168], be_s[56], wc_s[64], bc_s[16], wf_s[144];
    __shared__ float mean_s[4], inv_s[4];
    __shared__ float sA[168], sB0[168], sB1[168], sB2[168], sC[168];
    __shared__ float u[3][168];
    __shared__ float obuf[3][256];
    int t = blockIdx.x, b = blockIdx.y;
    int tid = threadIdx.x;

    hist_s[tid] = dHist[b*256 + tid];
    if (tid < 168) we_s[tid] = we[tid];
    if (tid < 56)  be_s[tid] = be[tid];
    if (tid < 64)  wc_s[tid] = wc[tid];
    if (tid < 16)  bc_s[tid] = bc[tid];
    if (tid < 144) wf_s[tid] = wf[tid];
    if (tid < 4){ mean_s[tid] = dMean[b*4+tid]; inv_s[tid] = dInv[b*4+tid]; }
    __syncthreads();
    float total = dTotal;

    // cell phase: 3 rows x 56 oc = 168 cells, one per thread
    if (tid < 168){
        int w = tid / 56, oc = tid - w*56;
        int p = t - 1 + w;
        int k3 = oc*3;
        float r00=0.f, r01=0.f, r02=0.f;
        float r10=0.f, r11=0.f, r12=0.f;
        float r20=0.f, r21=0.f, r22=0.f;
        if ((unsigned)p < 64u){
            float base = we_s[oc*3+0]*(float)(p>>3) + we_s[oc*3+1]*(float)(p&7) + be_s[oc];
            float w2 = we_s[oc*3+2];
            float tt0 = (lrelu(base + w2*(hist_s[0*64+p]/total)) - mean_s[0]) * inv_s[0];
            float tt1 = (lrelu(base + w2*(hist_s[1*64+p]/total)) - mean_s[1]) * inv_s[1];
            float tt2 = (lrelu(base + w2*(hist_s[2*64+p]/total)) - mean_s[2]) * inv_s[2];
            float tt3 = (lrelu(base + w2*(hist_s[3*64+p]/total)) - mean_s[3]) * inv_s[3];
            if (w == 1){
                #pragma unroll
                for (int m = 0; m < 16; m++){
                    float zm = lrelu(bc_s[m] + wc_s[m*4]*tt0 + wc_s[m*4+1]*tt1
                                             + wc_s[m*4+2]*tt2 + wc_s[m*4+3]*tt3);
                    r00 += zm * wf_s[m*9+0]; r01 += zm * wf_s[m*9+1]; r02 += zm * wf_s[m*9+2];
                    r10 += zm * wf_s[m*9+3]; r11 += zm * wf_s[m*9+4]; r12 += zm * wf_s[m*9+5];
                    r20 += zm * wf_s[m*9+6]; r21 += zm * wf_s[m*9+7]; r22 += zm * wf_s[m*9+8];
                }
            } else {
                int ib = (w == 0) ? 0 : 6;   // w=0 -> wf row i=0; w=2 -> i=2
                #pragma unroll
                for (int m = 0; m < 16; m++){
                    float zm = lrelu(bc_s[m] + wc_s[m*4]*tt0 + wc_s[m*4+1]*tt1
                                             + wc_s[m*4+2]*tt2 + wc_s[m*4+3]*tt3);
                    r00 += zm * wf_s[m*9+ib+0];
                    r01 += zm * wf_s[m*9+ib+1];
                    r02 += zm * wf_s[m*9+ib+2];
                }
            }
        }
        if (w == 0){
            sA[k3] = r00; sA[k3+1] = r01; sA[k3+2] = r02;
        } else if (w == 1){
            sB0[k3] = r00; sB0[k3+1] = r01; sB0[k3+2] = r02;
            sB1[k3] = r10; sB1[k3+1] = r11; sB1[k3+2] = r12;
            sB2[k3] = r20; sB2[k3+1] = r21; sB2[k3+2] = r22;
        } else {
            sC[k3] = r00; sC[k3+1] = r01; sC[k3+2] = r02;
        }
    }
    __syncthreads();

    for (int e = tid; e < 504; e += 256){
        int tbl = e / 168, k = e - tbl*168;
        float acc;
        if (tbl == 0){
            acc = sB1[k] + sB2[k];
            if (t > 0) acc += sA[k];
        } else if (tbl == 1){
            acc = sB0[k] + sB1[k] + sB2[k];
        } else {
            acc = sB0[k] + sB1[k];
            if (t < 63) acc += sC[k];
        }
        u[tbl][k] = acc;
    }
    __syncthreads();

    {
        int w = tid;
        int gwC = (w*56) >> 8;
        int gwL = ((w-1)*56) >> 8;
        int gwR = ((w+1)*56) >> 8;
        float base = bf[0];
        #pragma unroll
        for (int tbl = 0; tbl < 3; tbl++){
            float acc = base + u[tbl][gwC*3 + 1];
            if (w > 0)   acc += u[tbl][gwL*3 + 0];
            if (w < 255) acc += u[tbl][gwR*3 + 2];
            obuf[tbl][w] = lrelu(acc);
        }
    }
    __syncthreads();

    {
        int r = tid >> 6, c4 = tid & 63;
        int src = (r == 0) ? 0 : (r == 3 ? 2 : 1);
        float4 v = ((float4*)obuf[src])[c4];
        *(float4*)&out[((size_t)b << 16) | ((size_t)(t*4+r) << 8) | (size_t)(c4*4)] = v;
    }
}

extern "C" void kernel_launch(void* const* d_in, const int* in_sizes, int n_in,
                              void* d_out, int out_size){
    const float* x    = (const float*)d_in[0];
    const float* we   = (const float*)d_in[1];
    const float* be   = (const float*)d_in[2];
    const float* wc   = (const float*)d_in[3];
    const float* bc   = (const float*)d_in[4];
    const float* wfin = (const float*)d_in[5];
    const float* bfin = (const float*)d_in[6];
    const float* clo  = (const float*)d_in[7];
    const float* chi  = (const float*)d_in[8];
    float* out = (float*)d_out;

    k_pool_minmax<<<dim3(8,8,16), 256>>>(x, clo, chi);
    k_hist       <<<dim3(8,8,16), 256>>>(clo, chi);
    k_stats      <<<64, 256>>>(we, be);
    k_final      <<<dim3(64,16), 256>>>(we, be, wc, bc, wfin, bfin, out);
}